// round 7
// baseline (speedup 1.0000x reference)
#include <cuda_runtime.h>
#include <math.h>
#include <stdint.h>

#define C 16
#define D 512
#define CHUNK_ROWS 128
#define DPB 256            // dims per block-half in pass 1
#define NPAIRS (C*(C-1)/2)
#define NCHUNK 512         // row chunks (N=65536 / 128)
#define PBLK (NCHUNK*2)    // pass-1 partial blocks = 1024
#define GRPS 64            // stage-A groups
#define CPG (NCHUNK/GRPS)  // chunks per group = 8

// ---------------- device scratch (no allocations allowed) ----------------
__device__ float2 g_partial[PBLK * C * DPB];     // 32 MB
__device__ float2 g_pA[GRPS * C * D];            // 4 MB
__device__ int    g_counts[C];
__device__ float  g_mean[C * D];
__device__ float  g_within[C * D];
__device__ double g_pairsum[NPAIRS];
__device__ int    g_ids_is64;

__device__ __forceinline__ int get_id(const int* ids32, int i, int is64) {
    return is64 ? ids32[2 * i] : ids32[i];    // little-endian low word
}

// local (per-block) dtype detection: int64 ids < C have zero high words.
__device__ __forceinline__ int detect_is64(const int* ids32, int n) {
    int lim = n / 2; if (lim > 64) lim = 64;
    int any = 0;
    for (int i = 0; i < lim; i++) any |= ids32[2 * i + 1];
    return any == 0;
}

// ---------------- init ----------------
__global__ void k_init() {
    if (threadIdx.x < C) g_counts[threadIdx.x] = 0;
}

// ---------------- class counts (+ publish dtype flag) ----------------
__global__ void k_counts(const int* __restrict__ ids32, int n) {
    __shared__ int loc[C];
    if (threadIdx.x < C) loc[threadIdx.x] = 0;
    int is64;
    if (threadIdx.x == 0) {
        is64 = detect_is64(ids32, n);
        if (blockIdx.x == 0) g_ids_is64 = is64;   // for later kernels
        loc[C - 1] = loc[C - 1];                  // no-op
    }
    __syncthreads();
    // broadcast via shared
    __shared__ int s_is64;
    if (threadIdx.x == 0) s_is64 = detect_is64(ids32, n);
    __syncthreads();
    is64 = s_is64;
    for (int i = blockIdx.x * blockDim.x + threadIdx.x; i < n;
         i += gridDim.x * blockDim.x) {
        int c = get_id(ids32, i, is64) & (C - 1);
        atomicAdd(&loc[c], 1);
    }
    __syncthreads();
    if (threadIdx.x < C) atomicAdd(&g_counts[threadIdx.x], loc[threadIdx.x]);
}

// ---------------- pass 1: SMEM RMW accumulation, high-residency ------------
// block = (chunk of 128 rows) x (half of the 512 dims). Thread t owns one dim;
// acc index is computed (no branches), bank-conflict free. 1024 blocks ->
// ~7 blocks/SM resident (smem-limited), ~1770 threads/SM hides the RMW chain.
__global__ __launch_bounds__(256) void k_pass1(const float* __restrict__ hidden,
                                               const int* __restrict__ ids32) {
    __shared__ float2 acc[C * DPB];           // 32 KB
    __shared__ int cls[CHUNK_ROWS];
    int t = threadIdx.x;
    int half  = blockIdx.x & 1;
    int chunk = blockIdx.x >> 1;
    int rowBase = chunk * CHUNK_ROWS;

    for (int i = t; i < C * DPB; i += blockDim.x) acc[i] = make_float2(0.f, 0.f);
    if (t < CHUNK_ROWS)
        cls[t] = get_id(ids32, rowBase + t, g_ids_is64) & (C - 1);
    __syncthreads();

    int dim = half * DPB + t;
    const float* p = hidden + (size_t)rowBase * D + dim;
#pragma unroll 4
    for (int r = 0; r < CHUNK_ROWS; r++) {
        int c = cls[r];
        float v = p[(size_t)r * D];
        float2 a = acc[c * DPB + t];
        a.x += v;
        a.y = fmaf(v, v, a.y);
        acc[c * DPB + t] = a;
    }
    __syncthreads();

    float2* out = g_partial + (size_t)blockIdx.x * (C * DPB);
    for (int i = t; i < C * DPB; i += blockDim.x) out[i] = acc[i];
}

// ---------------- pass 2 stage A: wide coalesced partial reduction ---------
// item = c*512 + dim (8192 items). 64 groups x 8 chunks (blk = chunk*2+half).
__global__ __launch_bounds__(256) void k_pass2a() {
    int gid  = blockIdx.x * 256 + threadIdx.x;     // 0 .. 524287
    int item = gid & (C * D - 1);                  // 0 .. 8191
    int grp  = gid >> 13;                          // 0 .. 63
    int c    = item >> 9;
    int dim  = item & (D - 1);
    int half = dim >> 8;
    int t    = dim & (DPB - 1);
    const float2* p = g_partial + (size_t)c * DPB + t;
    float sx = 0.f, qq = 0.f;
#pragma unroll
    for (int k = 0; k < CPG; k++) {
        int chunk = grp * CPG + k;                 // 0 .. 511
        int blk   = (chunk << 1) | half;           // 0 .. 1023
        float2 v = p[(size_t)blk * (C * DPB)];
        sx += v.x; qq += v.y;
    }
    g_pA[grp * (C * D) + item] = make_float2(sx, qq);
}

// ---------------- pass 2 stage B: fp64 final -> mean / within --------------
__global__ __launch_bounds__(256) void k_pass2b() {
    int item = blockIdx.x * 256 + threadIdx.x;     // 0 .. 8191
    double sa = 0, sb = 0, sc = 0, sd = 0;
    double qa = 0, qb = 0, qc = 0, qd = 0;
#pragma unroll
    for (int g = 0; g < GRPS; g += 4) {
        float2 v0 = g_pA[(g + 0) * (C * D) + item];
        float2 v1 = g_pA[(g + 1) * (C * D) + item];
        float2 v2 = g_pA[(g + 2) * (C * D) + item];
        float2 v3 = g_pA[(g + 3) * (C * D) + item];
        sa += (double)v0.x; qa += (double)v0.y;
        sb += (double)v1.x; qb += (double)v1.y;
        sc += (double)v2.x; qc += (double)v2.y;
        sd += (double)v3.x; qd += (double)v3.y;
    }
    double sx = (sa + sb) + (sc + sd);
    double qq = (qa + qb) + (qc + qd);
    int c = item >> 9;
    double cnt  = (double)g_counts[c];
    double mean = sx / cnt;
    g_mean[item]   = (float)mean;
    g_within[item] = (float)(qq - sx * mean);
}

// ---------------- fp32 Lentz continued fraction for betainc ----------------
__device__ float betacf_f(float a, float b, float x) {
    const float FPMIN = 1e-30f;
    float qab = a + b, qap = a + 1.f, qam = a - 1.f;
    float cc = 1.f;
    float dd = 1.f - qab * x / qap;
    if (fabsf(dd) < FPMIN) dd = FPMIN;
    dd = 1.f / dd;
    float h = dd;
    for (int m = 1; m <= 250; m++) {
        float fm = (float)m, m2 = 2.f * fm;
        float aa = fm * (b - fm) * x / ((qam + m2) * (a + m2));
        dd = 1.f + aa * dd; if (fabsf(dd) < FPMIN) dd = FPMIN;
        cc = 1.f + aa / cc; if (fabsf(cc) < FPMIN) cc = FPMIN;
        dd = 1.f / dd;
        h *= dd * cc;
        aa = -(a + fm) * (qab + fm) * x / ((a + m2) * (qap + m2));
        dd = 1.f + aa * dd; if (fabsf(dd) < FPMIN) dd = FPMIN;
        cc = 1.f + aa / cc; if (fabsf(cc) < FPMIN) cc = FPMIN;
        dd = 1.f / dd;
        float del = dd * cc;
        h *= del;
        if (fabsf(del - 1.f) < 1e-7f) break;
    }
    return h;
}

// ---------------- pair kernel: x -> sort -> betainc(top-K) -> sum log ------
__global__ __launch_bounds__(D) void k_pairs(const int* __restrict__ dptr) {
    __shared__ float sx[D];
    __shared__ float sred[D];
    __shared__ float s_lnB;
    int t = threadIdx.x;

    int bid = blockIdx.x;
    int i = 0, rem = bid;
    while (rem >= C - 1 - i) { rem -= C - 1 - i; i++; }
    int j = i + 1 + rem;

    float ni = (float)g_counts[i], nj = (float)g_counts[j];
    float pc = ni + nj;
    float d2 = pc - 2.f;
    if (d2 == 0.f) d2 = 1e-5f;
    float b = d2 * 0.5f;

    if (t == 0) {
        double bd = (double)b;
        s_lnB = (float)(lgamma(0.5) + lgamma(bd) - lgamma(0.5 + bd));
    }

    float mi = g_mean[i * D + t],  mj = g_mean[j * D + t];
    float wi = g_within[i * D + t], wj = g_within[j * D + t];
    float hd   = (mi - mj) * 0.5f;
    float betw = hd * hd * pc;
    float x = betw / (betw + wi + wj);
    x = fminf(fmaxf(x, 1e-37f), 1.f - 1e-5f);
    sx[t] = x;
    __syncthreads();

    for (int k = 2; k <= D; k <<= 1) {
        for (int jj = k >> 1; jj > 0; jj >>= 1) {
            int ixj = t ^ jj;
            if (ixj > t) {
                float a0 = sx[t], b0 = sx[ixj];
                bool desc = ((t & k) == 0);
                if (desc ? (a0 < b0) : (a0 > b0)) { sx[t] = b0; sx[ixj] = a0; }
            }
            __syncthreads();
        }
    }

    int K = 64;
    if (dptr) {
        int kv = dptr[0];
        if (kv >= 1 && kv <= D) K = kv;
    }

    const float a = 0.5f;
    float val = 0.f;
    if (t < K) {
        float xv  = sx[t];
        float lnB = s_lnB;
        float lbt = a * logf(xv) + b * log1pf(-xv) - lnB;
        float thresh = (a + 1.f) / (a + b + 2.f);
        float logI;
        if (xv < thresh) {
            float cf = betacf_f(a, b, xv);
            if (cf < 1e-30f) cf = 1e-30f;
            logI = lbt + logf(cf) - logf(a);
        } else {
            float cf   = betacf_f(b, a, 1.f - xv);
            float tail = expf(lbt) * cf / b;
            if (tail > 0.99999994f) tail = 0.99999994f;
            logI = log1pf(-tail);
        }
        val = logI;
    }
    sred[t] = val;
    __syncthreads();
    for (int s = D / 2; s > 0; s >>= 1) {
        if (t < s) sred[t] += sred[t + s];
        __syncthreads();
    }
    if (t == 0) g_pairsum[bid] = (double)sred[0];
}

// ---------------- final scalar reduce (parallel, fixed tree order) ---------
__global__ void k_final(float* out) {
    __shared__ double sr[128];
    int t = threadIdx.x;
    sr[t] = (t < NPAIRS) ? g_pairsum[t] : 0.0;
    __syncthreads();
    for (int s = 64; s > 0; s >>= 1) {
        if (t < s) sr[t] += sr[t + s];
        __syncthreads();
    }
    if (t == 0) out[0] = (float)(-sr[0]);
}

// ---------------- launch ----------------
extern "C" void kernel_launch(void* const* d_in, const int* in_sizes, int n_in,
                              void* d_out, int out_size) {
    const float* hidden = (const float*)d_in[0];
    const int*   ids32  = (const int*)d_in[1];
    const int*   dptr   = (n_in > 2) ? (const int*)d_in[2] : nullptr;

    int N = in_sizes[0] / D;            // 65536

    k_init  <<<1, 32>>>();
    k_counts<<<128, 256>>>(ids32, N);
    k_pass1 <<<PBLK, 256>>>(hidden, ids32);
    k_pass2a<<<(GRPS * C * D) / 256, 256>>>();
    k_pass2b<<<(C * D) / 256, 256>>>();
    k_pairs <<<NPAIRS, D>>>(dptr);
    k_final <<<1, 128>>>((float*)d_out);
}

// round 8
// speedup vs baseline: 1.1652x; 1.1652x over previous
#include <cuda_runtime.h>
#include <math.h>
#include <stdint.h>

#define C 16
#define D 512
#define CHUNK_ROWS 256
#define DPB 256            // dims per block-half in pass 1
#define NPAIRS (C*(C-1)/2)
#define NCHUNK 256         // row chunks (N=65536 / 256)
#define PBLK (NCHUNK*2)    // pass-1 partial blocks = 512
#define GRPS 32            // stage-A groups
#define CPG (NCHUNK/GRPS)  // chunks per group = 8

// ---------------- device scratch (no allocations allowed) ----------------
__device__ float2 g_partial[PBLK * C * DPB];     // 16 MB
__device__ float2 g_pA[GRPS * C * D];            // 2 MB
__device__ int    g_counts[C];
__device__ float  g_mean[C * D];
__device__ float  g_within[C * D];
__device__ float  g_lnB[NPAIRS];
__device__ double g_pairsum[NPAIRS];
__device__ int    g_ids_is64;

__device__ __forceinline__ int get_id(const int* ids32, int i, int is64) {
    return is64 ? ids32[2 * i] : ids32[i];    // little-endian low word
}

__device__ __forceinline__ int detect_is64(const int* ids32, int n) {
    int lim = n / 2; if (lim > 64) lim = 64;
    int any = 0;
    for (int i = 0; i < lim; i++) any |= ids32[2 * i + 1];
    return any == 0;
}

// ---------------- init ----------------
__global__ void k_init() {
    if (threadIdx.x < C) g_counts[threadIdx.x] = 0;
}

// ---------------- class counts (+ publish dtype flag) ----------------
__global__ void k_counts(const int* __restrict__ ids32, int n) {
    __shared__ int loc[C];
    __shared__ int s_is64;
    if (threadIdx.x < C) loc[threadIdx.x] = 0;
    if (threadIdx.x == 0) {
        int is64 = detect_is64(ids32, n);
        s_is64 = is64;
        if (blockIdx.x == 0) g_ids_is64 = is64;
    }
    __syncthreads();
    int is64 = s_is64;
    for (int i = blockIdx.x * blockDim.x + threadIdx.x; i < n;
         i += gridDim.x * blockDim.x) {
        int c = get_id(ids32, i, is64) & (C - 1);
        atomicAdd(&loc[c], 1);
    }
    __syncthreads();
    if (threadIdx.x < C) atomicAdd(&g_counts[threadIdx.x], loc[threadIdx.x]);
}

// ---------------- per-pair ln B(1/2, d2/2) precompute (fp64, parallel) -----
__global__ void k_lnB() {
    int p = threadIdx.x;
    if (p < NPAIRS) {
        int i = 0, rem = p;
        while (rem >= C - 1 - i) { rem -= C - 1 - i; i++; }
        int j = i + 1 + rem;
        float ni = (float)g_counts[i], nj = (float)g_counts[j];
        float pc = ni + nj;
        float d2 = pc - 2.f;
        if (d2 == 0.f) d2 = 1e-5f;
        float b = d2 * 0.5f;
        double bd = (double)b;
        g_lnB[p] = (float)(lgamma(0.5) + lgamma(bd) - lgamma(0.5 + bd));
    }
}

// ---------------- pass 1: SMEM RMW accumulation (R6 geometry) --------------
// block = (chunk of 256 rows) x (half of the 512 dims). Thread t owns one dim.
// Loads batched 4 rows ahead of the RMW chain to keep MLP up; accumulation
// order per (class,dim) is unchanged (row order) -> bit-identical partials.
__global__ __launch_bounds__(256) void k_pass1(const float* __restrict__ hidden,
                                               const int* __restrict__ ids32) {
    __shared__ float2 acc[C * DPB];           // 32 KB
    __shared__ int cls[CHUNK_ROWS];
    int t = threadIdx.x;
    int half  = blockIdx.x & 1;
    int chunk = blockIdx.x >> 1;
    int rowBase = chunk * CHUNK_ROWS;

    for (int i = t; i < C * DPB; i += blockDim.x) acc[i] = make_float2(0.f, 0.f);
    cls[t] = get_id(ids32, rowBase + t, g_ids_is64) & (C - 1);
    __syncthreads();

    int dim = half * DPB + t;
    const float* p = hidden + (size_t)rowBase * D + dim;
#pragma unroll 2
    for (int r = 0; r < CHUNK_ROWS; r += 4) {
        float v0 = p[(size_t)(r + 0) * D];
        float v1 = p[(size_t)(r + 1) * D];
        float v2 = p[(size_t)(r + 2) * D];
        float v3 = p[(size_t)(r + 3) * D];
        int c0 = cls[r], c1 = cls[r + 1], c2 = cls[r + 2], c3 = cls[r + 3];
        float2 a;
        a = acc[c0 * DPB + t]; a.x += v0; a.y = fmaf(v0, v0, a.y); acc[c0 * DPB + t] = a;
        a = acc[c1 * DPB + t]; a.x += v1; a.y = fmaf(v1, v1, a.y); acc[c1 * DPB + t] = a;
        a = acc[c2 * DPB + t]; a.x += v2; a.y = fmaf(v2, v2, a.y); acc[c2 * DPB + t] = a;
        a = acc[c3 * DPB + t]; a.x += v3; a.y = fmaf(v3, v3, a.y); acc[c3 * DPB + t] = a;
    }
    __syncthreads();

    float2* out = g_partial + (size_t)blockIdx.x * (C * DPB);
    for (int i = t; i < C * DPB; i += blockDim.x) out[i] = acc[i];
}

// ---------------- pass 2 stage A: wide coalesced partial reduction ---------
__global__ __launch_bounds__(256) void k_pass2a() {
    int gid  = blockIdx.x * 256 + threadIdx.x;     // 0 .. 262143
    int item = gid & (C * D - 1);                  // 0 .. 8191
    int grp  = gid >> 13;                          // 0 .. 31
    int c    = item >> 9;
    int dim  = item & (D - 1);
    int half = dim >> 8;
    int t    = dim & (DPB - 1);
    const float2* p = g_partial + (size_t)c * DPB + t;
    float sx = 0.f, qq = 0.f;
#pragma unroll
    for (int k = 0; k < CPG; k++) {
        int chunk = grp * CPG + k;                 // 0 .. 255
        int blk   = (chunk << 1) | half;           // 0 .. 511
        float2 v = p[(size_t)blk * (C * DPB)];
        sx += v.x; qq += v.y;
    }
    g_pA[grp * (C * D) + item] = make_float2(sx, qq);
}

// ---------------- pass 2 stage B: fp64 final -> mean / within --------------
__global__ __launch_bounds__(256) void k_pass2b() {
    int item = blockIdx.x * 256 + threadIdx.x;     // 0 .. 8191
    double sx = 0.0, qq = 0.0;
#pragma unroll
    for (int g = 0; g < GRPS; g++) {
        float2 v = g_pA[g * (C * D) + item];
        sx += (double)v.x; qq += (double)v.y;
    }
    int c = item >> 9;
    double cnt  = (double)g_counts[c];
    double mean = sx / cnt;
    g_mean[item]   = (float)mean;
    g_within[item] = (float)(qq - sx * mean);
}

// ---------------- fp32 Lentz continued fraction for betainc ----------------
__device__ float betacf_f(float a, float b, float x) {
    const float FPMIN = 1e-30f;
    float qab = a + b, qap = a + 1.f, qam = a - 1.f;
    float cc = 1.f;
    float dd = 1.f - qab * x / qap;
    if (fabsf(dd) < FPMIN) dd = FPMIN;
    dd = 1.f / dd;
    float h = dd;
    for (int m = 1; m <= 250; m++) {
        float fm = (float)m, m2 = 2.f * fm;
        float aa = fm * (b - fm) * x / ((qam + m2) * (a + m2));
        dd = 1.f + aa * dd; if (fabsf(dd) < FPMIN) dd = FPMIN;
        cc = 1.f + aa / cc; if (fabsf(cc) < FPMIN) cc = FPMIN;
        dd = 1.f / dd;
        h *= dd * cc;
        aa = -(a + fm) * (qab + fm) * x / ((a + m2) * (qap + m2));
        dd = 1.f + aa * dd; if (fabsf(dd) < FPMIN) dd = FPMIN;
        cc = 1.f + aa / cc; if (fabsf(cc) < FPMIN) cc = FPMIN;
        dd = 1.f / dd;
        float del = dd * cc;
        h *= del;
        if (fabsf(del - 1.f) < 1e-7f) break;
    }
    return h;
}

// ---------------- pair kernel: x -> sort -> betainc(top-K) -> sum log ------
__global__ __launch_bounds__(D) void k_pairs(const int* __restrict__ dptr) {
    __shared__ float sx[D];
    __shared__ float sred[D];
    int t = threadIdx.x;

    int bid = blockIdx.x;
    int i = 0, rem = bid;
    while (rem >= C - 1 - i) { rem -= C - 1 - i; i++; }
    int j = i + 1 + rem;

    float ni = (float)g_counts[i], nj = (float)g_counts[j];
    float pc = ni + nj;
    float d2 = pc - 2.f;
    if (d2 == 0.f) d2 = 1e-5f;
    float b = d2 * 0.5f;

    float mi = g_mean[i * D + t],  mj = g_mean[j * D + t];
    float wi = g_within[i * D + t], wj = g_within[j * D + t];
    float hd   = (mi - mj) * 0.5f;
    float betw = hd * hd * pc;
    float x = betw / (betw + wi + wj);
    x = fminf(fmaxf(x, 1e-37f), 1.f - 1e-5f);
    sx[t] = x;
    __syncthreads();

    for (int k = 2; k <= D; k <<= 1) {
        for (int jj = k >> 1; jj > 0; jj >>= 1) {
            int ixj = t ^ jj;
            if (ixj > t) {
                float a0 = sx[t], b0 = sx[ixj];
                bool desc = ((t & k) == 0);
                if (desc ? (a0 < b0) : (a0 > b0)) { sx[t] = b0; sx[ixj] = a0; }
            }
            __syncthreads();
        }
    }

    int K = 64;
    if (dptr) {
        int kv = dptr[0];
        if (kv >= 1 && kv <= D) K = kv;
    }

    const float a = 0.5f;
    float val = 0.f;
    if (t < K) {
        float xv  = sx[t];
        float lnB = g_lnB[bid];
        float lbt = a * logf(xv) + b * log1pf(-xv) - lnB;
        float thresh = (a + 1.f) / (a + b + 2.f);
        float logI;
        if (xv < thresh) {
            float cf = betacf_f(a, b, xv);
            if (cf < 1e-30f) cf = 1e-30f;
            logI = lbt + logf(cf) - logf(a);
        } else {
            float cf   = betacf_f(b, a, 1.f - xv);
            float tail = expf(lbt) * cf / b;
            if (tail > 0.99999994f) tail = 0.99999994f;
            logI = log1pf(-tail);
        }
        val = logI;
    }
    sred[t] = val;
    __syncthreads();
    for (int s = D / 2; s > 0; s >>= 1) {
        if (t < s) sred[t] += sred[t + s];
        __syncthreads();
    }
    if (t == 0) g_pairsum[bid] = (double)sred[0];
}

// ---------------- final scalar reduce (parallel, fixed tree order) ---------
__global__ void k_final(float* out) {
    __shared__ double sr[128];
    int t = threadIdx.x;
    sr[t] = (t < NPAIRS) ? g_pairsum[t] : 0.0;
    __syncthreads();
    for (int s = 64; s > 0; s >>= 1) {
        if (t < s) sr[t] += sr[t + s];
        __syncthreads();
    }
    if (t == 0) out[0] = (float)(-sr[0]);
}

// ---------------- launch ----------------
extern "C" void kernel_launch(void* const* d_in, const int* in_sizes, int n_in,
                              void* d_out, int out_size) {
    const float* hidden = (const float*)d_in[0];
    const int*   ids32  = (const int*)d_in[1];
    const int*   dptr   = (n_in > 2) ? (const int*)d_in[2] : nullptr;

    int N = in_sizes[0] / D;            // 65536

    k_init  <<<1, 32>>>();                               // launch 1
    k_counts<<<128, 256>>>(ids32, N);                    // launch 2
    k_lnB   <<<1, 128>>>();                              // launch 3
    k_pass1 <<<PBLK, 256>>>(hidden, ids32);              // launch 4 (profiled)
    k_pass2a<<<(GRPS * C * D) / 256, 256>>>();           // launch 5
    k_pass2b<<<(C * D) / 256, 256>>>();                  // launch 6
    k_pairs <<<NPAIRS, D>>>(dptr);                       // launch 7
    k_final <<<1, 128>>>((float*)d_out);                 // launch 8
}